// round 1
// baseline (speedup 1.0000x reference)
#include <cuda_runtime.h>

#define N_NODES 100000
#define N_EDGES 1600000
#define IN_DIM 256
#define HID 128
#define N_GRAPHS 64
#define OUT_MF 489
#define OUT_BP 1943
#define OUT_CC 320

// ---------------- scratch (device globals; no runtime alloc) ----------------
__device__ __align__(16) float g_h[N_NODES * HID];    // hs (pre-scaled gemm out)
__device__ __align__(16) float g_h2[N_NODES * HID];   // activated layer output
__device__ float g_dis[N_NODES];
__device__ int   g_deg[N_NODES];
__device__ int   g_row_ptr[N_NODES + 1];
__device__ int   g_cursor[N_NODES];
__device__ int   g_col[N_EDGES];
__device__ __align__(16) float g_pool[N_GRAPHS * HID];
__device__ __align__(16) float g_pooled[N_GRAPHS * HID];
__device__ int   g_cnt[N_GRAPHS];

// ---------------- zero init (graph-replay safe) ----------------
__global__ void k_zero() {
    int idx = blockIdx.x * blockDim.x + threadIdx.x;
    int stride = gridDim.x * blockDim.x;
    for (int i = idx; i < N_NODES; i += stride) g_deg[i] = 0;
    if (idx < N_GRAPHS * HID) g_pool[idx] = 0.f;
    if (idx < N_GRAPHS) g_cnt[idx] = 0;
}

// ---------------- in-degree count ----------------
__global__ void k_count(const int* __restrict__ dst) {
    int e = blockIdx.x * blockDim.x + threadIdx.x;
    if (e < N_EDGES) atomicAdd(&g_deg[dst[e]], 1);
}

// ---------------- single-block exclusive scan over degrees ----------------
// Also writes cursor copy and deg_inv_sqrt.
__global__ void k_scan() {
    __shared__ int warp_sums[32];
    __shared__ int s_base;
    const int tid = threadIdx.x;
    const int lane = tid & 31;
    const int wid = tid >> 5;
    if (tid == 0) s_base = 0;
    __syncthreads();

    for (int base = 0; base < N_NODES; base += 4096) {
        int i0 = base + tid * 4;
        int v0 = (i0 + 0 < N_NODES) ? g_deg[i0 + 0] : 0;
        int v1 = (i0 + 1 < N_NODES) ? g_deg[i0 + 1] : 0;
        int v2 = (i0 + 2 < N_NODES) ? g_deg[i0 + 2] : 0;
        int v3 = (i0 + 3 < N_NODES) ? g_deg[i0 + 3] : 0;
        int t = v0 + v1 + v2 + v3;

        // warp inclusive scan of t
        int x = t;
        #pragma unroll
        for (int s = 1; s < 32; s <<= 1) {
            int y = __shfl_up_sync(0xFFFFFFFFu, x, s);
            if (lane >= s) x += y;
        }
        if (lane == 31) warp_sums[wid] = x;
        __syncthreads();
        if (wid == 0) {
            int w = warp_sums[lane];
            #pragma unroll
            for (int s = 1; s < 32; s <<= 1) {
                int y = __shfl_up_sync(0xFFFFFFFFu, w, s);
                if (lane >= s) w += y;
            }
            warp_sums[lane] = w;
        }
        __syncthreads();

        int warp_excl = (wid == 0) ? 0 : warp_sums[wid - 1];
        int off = s_base + warp_excl + (x - t);  // exclusive offset for this thread

        int e0 = off;
        int e1 = e0 + v0;
        int e2 = e1 + v1;
        int e3 = e2 + v2;
        if (i0 + 0 < N_NODES) { g_row_ptr[i0 + 0] = e0; g_cursor[i0 + 0] = e0; g_dis[i0 + 0] = rsqrtf((float)v0 + 1.0f); }
        if (i0 + 1 < N_NODES) { g_row_ptr[i0 + 1] = e1; g_cursor[i0 + 1] = e1; g_dis[i0 + 1] = rsqrtf((float)v1 + 1.0f); }
        if (i0 + 2 < N_NODES) { g_row_ptr[i0 + 2] = e2; g_cursor[i0 + 2] = e2; g_dis[i0 + 2] = rsqrtf((float)v2 + 1.0f); }
        if (i0 + 3 < N_NODES) { g_row_ptr[i0 + 3] = e3; g_cursor[i0 + 3] = e3; g_dis[i0 + 3] = rsqrtf((float)v3 + 1.0f); }

        __syncthreads();
        if (tid == 0) s_base += warp_sums[31];
        __syncthreads();
    }
    if (threadIdx.x == 0) g_row_ptr[N_NODES] = s_base;
}

// ---------------- CSR fill (dst-sorted adjacency) ----------------
__global__ void k_fill(const int* __restrict__ src, const int* __restrict__ dst) {
    int e = blockIdx.x * blockDim.x + threadIdx.x;
    if (e < N_EDGES) {
        int d = dst[e];
        int p = atomicAdd(&g_cursor[d], 1);
        g_col[p] = src[e];
    }
}

// ---------------- GEMM: out = (A @ W) * dis[row], writes g_h ----------------
// 128x128 block tile, BK=32, 8x8 microtile per thread, 256 threads.
template <int K, bool FROM_X>
__global__ void __launch_bounds__(256, 2) k_gemm(const float* __restrict__ Aext,
                                                 const float* __restrict__ W) {
    __shared__ float As[128][33];
    __shared__ float Ws[32][HID];

    const float* A = FROM_X ? Aext : g_h2;
    const int tid = threadIdx.x;
    const int row0 = blockIdx.x * 128;
    const int tm = tid >> 4;      // 0..15
    const int tn = tid & 15;      // 0..15
    const int tm8 = tm * 8;
    const int tn8 = tn * 8;

    float acc[8][8];
    #pragma unroll
    for (int m = 0; m < 8; m++)
        #pragma unroll
        for (int n = 0; n < 8; n++) acc[m][n] = 0.f;

    for (int kk = 0; kk < K; kk += 32) {
        // load A tile: 128 rows x 32 k (float4 per thread x4), store [row][k]
        #pragma unroll
        for (int j = 0; j < 4; j++) {
            int f = tid + 256 * j;      // 0..1023
            int r = f >> 3;
            int k4 = (f & 7) * 4;
            int row = row0 + r;
            float4 v = make_float4(0.f, 0.f, 0.f, 0.f);
            if (row < N_NODES) v = *(const float4*)&A[row * K + kk + k4];
            As[r][k4 + 0] = v.x;
            As[r][k4 + 1] = v.y;
            As[r][k4 + 2] = v.z;
            As[r][k4 + 3] = v.w;
        }
        // load W tile: 32 k x 128 cols
        #pragma unroll
        for (int j = 0; j < 4; j++) {
            int f = tid + 256 * j;
            int k = f >> 5;
            int c4 = (f & 31) * 4;
            *(float4*)&Ws[k][c4] = *(const float4*)&W[(kk + k) * HID + c4];
        }
        __syncthreads();

        #pragma unroll
        for (int k = 0; k < 32; k++) {
            float a[8], b[8];
            #pragma unroll
            for (int m = 0; m < 8; m++) a[m] = As[tm8 + m][k];
            float4 b0 = *(const float4*)&Ws[k][tn8];
            float4 b1 = *(const float4*)&Ws[k][tn8 + 4];
            b[0] = b0.x; b[1] = b0.y; b[2] = b0.z; b[3] = b0.w;
            b[4] = b1.x; b[5] = b1.y; b[6] = b1.z; b[7] = b1.w;
            #pragma unroll
            for (int m = 0; m < 8; m++)
                #pragma unroll
                for (int n = 0; n < 8; n++) acc[m][n] = fmaf(a[m], b[n], acc[m][n]);
        }
        __syncthreads();
    }

    // epilogue: scale by dis[row], write hs
    #pragma unroll
    for (int m = 0; m < 8; m++) {
        int row = row0 + tm8 + m;
        if (row < N_NODES) {
            float d = g_dis[row];
            float4 o0 = make_float4(acc[m][0] * d, acc[m][1] * d, acc[m][2] * d, acc[m][3] * d);
            float4 o1 = make_float4(acc[m][4] * d, acc[m][5] * d, acc[m][6] * d, acc[m][7] * d);
            *(float4*)&g_h[row * HID + tn8] = o0;
            *(float4*)&g_h[row * HID + tn8 + 4] = o1;
        }
    }
}

// ---------------- edge aggregation (pull, CSR, warp per node) ----------------
// g_h2[i] = relu(dis_i * (hs_i + sum_{j in N(i)} hs_j) + b)
__global__ void k_agg(const float* __restrict__ bias) {
    int node = (blockIdx.x * blockDim.x + threadIdx.x) >> 5;
    int lane = threadIdx.x & 31;
    if (node >= N_NODES) return;

    const float4* hs4 = (const float4*)g_h;
    int beg = g_row_ptr[node];
    int end = g_row_ptr[node + 1];

    float4 a0 = hs4[node * 32 + lane];  // self contribution (hs includes dis)
    float4 a1 = make_float4(0.f, 0.f, 0.f, 0.f);
    float4 a2 = make_float4(0.f, 0.f, 0.f, 0.f);
    float4 a3 = make_float4(0.f, 0.f, 0.f, 0.f);

    int e = beg;
    for (; e + 4 <= end; e += 4) {
        int s0 = g_col[e + 0];
        int s1 = g_col[e + 1];
        int s2 = g_col[e + 2];
        int s3 = g_col[e + 3];
        float4 v0 = hs4[s0 * 32 + lane];
        float4 v1 = hs4[s1 * 32 + lane];
        float4 v2 = hs4[s2 * 32 + lane];
        float4 v3 = hs4[s3 * 32 + lane];
        a0.x += v0.x; a0.y += v0.y; a0.z += v0.z; a0.w += v0.w;
        a1.x += v1.x; a1.y += v1.y; a1.z += v1.z; a1.w += v1.w;
        a2.x += v2.x; a2.y += v2.y; a2.z += v2.z; a2.w += v2.w;
        a3.x += v3.x; a3.y += v3.y; a3.z += v3.z; a3.w += v3.w;
    }
    for (; e < end; e++) {
        int s = g_col[e];
        float4 v = hs4[s * 32 + lane];
        a0.x += v.x; a0.y += v.y; a0.z += v.z; a0.w += v.w;
    }
    a0.x += a1.x + a2.x + a3.x;
    a0.y += a1.y + a2.y + a3.y;
    a0.z += a1.z + a2.z + a3.z;
    a0.w += a1.w + a2.w + a3.w;

    float d = g_dis[node];
    float4 bb = ((const float4*)bias)[lane];
    float4 r;
    r.x = fmaxf(fmaf(d, a0.x, bb.x), 0.f);
    r.y = fmaxf(fmaf(d, a0.y, bb.y), 0.f);
    r.z = fmaxf(fmaf(d, a0.z, bb.z), 0.f);
    r.w = fmaxf(fmaf(d, a0.w, bb.w), 0.f);
    ((float4*)g_h2)[node * 32 + lane] = r;
}

// ---------------- pooling: segment sums over sorted batch ----------------
__global__ void k_pool(const int* __restrict__ batch) {
    const int col = threadIdx.x;          // 0..127
    const int n0 = blockIdx.x * 128;
    const int nend = min(n0 + 128, N_NODES);
    if (n0 >= N_NODES) return;

    float acc = 0.f;
    int cnt = 0;
    int cur = batch[n0];
    for (int nd = n0; nd < nend; nd++) {
        int g = batch[nd];
        if (g != cur) {
            atomicAdd(&g_pool[cur * HID + col], acc);
            if (col == 0) atomicAdd(&g_cnt[cur], cnt);
            acc = 0.f; cnt = 0; cur = g;
        }
        acc += g_h2[nd * HID + col];
        cnt++;
    }
    atomicAdd(&g_pool[cur * HID + col], acc);
    if (col == 0) atomicAdd(&g_cnt[cur], cnt);
}

__global__ void k_pdiv() {
    int idx = blockIdx.x * blockDim.x + threadIdx.x;
    if (idx < N_GRAPHS * HID) {
        float c = (float)g_cnt[idx / HID];
        g_pooled[idx] = g_pool[idx] / fmaxf(c, 1.0f);
    }
}

// ---------------- output heads ----------------
__global__ void k_heads(const float* __restrict__ Wmf, const float* __restrict__ bmf,
                        const float* __restrict__ Wbp, const float* __restrict__ bbp,
                        const float* __restrict__ Wcc, const float* __restrict__ bcc,
                        float* __restrict__ out) {
    const int TOT = OUT_MF + OUT_BP + OUT_CC;  // 2752
    int idx = blockIdx.x * blockDim.x + threadIdx.x;
    if (idx >= N_GRAPHS * TOT) return;
    int g = idx / TOT;
    int c = idx % TOT;

    const float* W;
    const float* b;
    float* o;
    int od, cc;
    if (c < OUT_MF) {
        W = Wmf; b = bmf; od = OUT_MF; cc = c;
        o = out;
    } else if (c < OUT_MF + OUT_BP) {
        W = Wbp; b = bbp; od = OUT_BP; cc = c - OUT_MF;
        o = out + N_GRAPHS * OUT_MF;
    } else {
        W = Wcc; b = bcc; od = OUT_CC; cc = c - OUT_MF - OUT_BP;
        o = out + N_GRAPHS * (OUT_MF + OUT_BP);
    }

    const float* p = g_pooled + g * HID;
    float acc = b[cc];
    #pragma unroll 8
    for (int k = 0; k < HID; k++) acc = fmaf(p[k], W[k * od + cc], acc);
    o[g * od + cc] = acc;
}

// ---------------- launch ----------------
extern "C" void kernel_launch(void* const* d_in, const int* in_sizes, int n_in,
                              void* d_out, int out_size) {
    const float* x    = (const float*)d_in[0];
    const int*   ei   = (const int*)d_in[1];
    const int*   bat  = (const int*)d_in[2];
    const float* W1   = (const float*)d_in[3];
    const float* b1   = (const float*)d_in[4];
    const float* W2   = (const float*)d_in[5];
    const float* b2   = (const float*)d_in[6];
    const float* Wmf  = (const float*)d_in[7];
    const float* bmf  = (const float*)d_in[8];
    const float* Wbp  = (const float*)d_in[9];
    const float* bbp  = (const float*)d_in[10];
    const float* Wcc  = (const float*)d_in[11];
    const float* bcc  = (const float*)d_in[12];
    float* out = (float*)d_out;

    const int* src = ei;
    const int* dst = ei + N_EDGES;

    const int EBLK = (N_EDGES + 255) / 256;
    const int GEMM_BLOCKS = (N_NODES + 127) / 128;

    k_zero<<<512, 256>>>();
    k_count<<<EBLK, 256>>>(dst);
    k_scan<<<1, 1024>>>();
    k_fill<<<EBLK, 256>>>(src, dst);

    // layer 1
    k_gemm<IN_DIM, true><<<GEMM_BLOCKS, 256>>>(x, W1);
    k_agg<<<(N_NODES * 32 + 255) / 256, 256>>>(b1);

    // layer 2
    k_gemm<HID, false><<<GEMM_BLOCKS, 256>>>(nullptr, W2);
    k_agg<<<(N_NODES * 32 + 255) / 256, 256>>>(b2);

    // pool + heads
    k_pool<<<(N_NODES + 127) / 128, 128>>>(bat);
    k_pdiv<<<(N_GRAPHS * HID + 255) / 256, 256>>>();
    k_heads<<<(N_GRAPHS * (OUT_MF + OUT_BP + OUT_CC) + 255) / 256, 256>>>(
        Wmf, bmf, Wbp, bbp, Wcc, bcc, out);
}

// round 2
// speedup vs baseline: 1.1611x; 1.1611x over previous
#include <cuda_runtime.h>
#include <cstdint>

#define N_NODES 100000
#define N_EDGES 1600000
#define IN_DIM 256
#define HID 128
#define N_GRAPHS 64
#define OUT_MF 489
#define OUT_BP 1943
#define OUT_CC 320

// ---------------- scratch (device globals; no runtime alloc) ----------------
__device__ __align__(16) float g_h[N_NODES * HID];    // hs (pre-scaled gemm out)
__device__ __align__(16) float g_h2[N_NODES * HID];   // activated layer output
__device__ float g_dis[N_NODES];
__device__ int   g_deg[N_NODES];
__device__ int   g_row_ptr[N_NODES + 1];
__device__ int   g_cursor[N_NODES];
__device__ int   g_col[N_EDGES];
__device__ __align__(16) float g_pool[N_GRAPHS * HID];
__device__ __align__(16) float g_pooled[N_GRAPHS * HID];
__device__ int   g_cnt[N_GRAPHS];

// ---------------- zero init (graph-replay safe) ----------------
__global__ void k_zero() {
    int idx = blockIdx.x * blockDim.x + threadIdx.x;
    int stride = gridDim.x * blockDim.x;
    for (int i = idx; i < N_NODES; i += stride) g_deg[i] = 0;
    if (idx < N_GRAPHS * HID) g_pool[idx] = 0.f;
    if (idx < N_GRAPHS) g_cnt[idx] = 0;
}

// ---------------- in-degree count ----------------
__global__ void k_count(const int* __restrict__ dst) {
    int e = blockIdx.x * blockDim.x + threadIdx.x;
    if (e < N_EDGES) atomicAdd(&g_deg[dst[e]], 1);
}

// ---------------- single-block exclusive scan over degrees ----------------
__global__ void k_scan() {
    __shared__ int warp_sums[32];
    __shared__ int s_base;
    const int tid = threadIdx.x;
    const int lane = tid & 31;
    const int wid = tid >> 5;
    if (tid == 0) s_base = 0;
    __syncthreads();

    for (int base = 0; base < N_NODES; base += 4096) {
        int i0 = base + tid * 4;
        int v0 = (i0 + 0 < N_NODES) ? g_deg[i0 + 0] : 0;
        int v1 = (i0 + 1 < N_NODES) ? g_deg[i0 + 1] : 0;
        int v2 = (i0 + 2 < N_NODES) ? g_deg[i0 + 2] : 0;
        int v3 = (i0 + 3 < N_NODES) ? g_deg[i0 + 3] : 0;
        int t = v0 + v1 + v2 + v3;

        int x = t;
        #pragma unroll
        for (int s = 1; s < 32; s <<= 1) {
            int y = __shfl_up_sync(0xFFFFFFFFu, x, s);
            if (lane >= s) x += y;
        }
        if (lane == 31) warp_sums[wid] = x;
        __syncthreads();
        if (wid == 0) {
            int w = warp_sums[lane];
            #pragma unroll
            for (int s = 1; s < 32; s <<= 1) {
                int y = __shfl_up_sync(0xFFFFFFFFu, w, s);
                if (lane >= s) w += y;
            }
            warp_sums[lane] = w;
        }
        __syncthreads();

        int warp_excl = (wid == 0) ? 0 : warp_sums[wid - 1];
        int off = s_base + warp_excl + (x - t);

        int e0 = off;
        int e1 = e0 + v0;
        int e2 = e1 + v1;
        int e3 = e2 + v2;
        if (i0 + 0 < N_NODES) { g_row_ptr[i0 + 0] = e0; g_cursor[i0 + 0] = e0; g_dis[i0 + 0] = rsqrtf((float)v0 + 1.0f); }
        if (i0 + 1 < N_NODES) { g_row_ptr[i0 + 1] = e1; g_cursor[i0 + 1] = e1; g_dis[i0 + 1] = rsqrtf((float)v1 + 1.0f); }
        if (i0 + 2 < N_NODES) { g_row_ptr[i0 + 2] = e2; g_cursor[i0 + 2] = e2; g_dis[i0 + 2] = rsqrtf((float)v2 + 1.0f); }
        if (i0 + 3 < N_NODES) { g_row_ptr[i0 + 3] = e3; g_cursor[i0 + 3] = e3; g_dis[i0 + 3] = rsqrtf((float)v3 + 1.0f); }

        __syncthreads();
        if (tid == 0) s_base += warp_sums[31];
        __syncthreads();
    }
    if (threadIdx.x == 0) g_row_ptr[N_NODES] = s_base;
}

// ---------------- CSR fill (dst-sorted adjacency) ----------------
__global__ void k_fill(const int* __restrict__ src, const int* __restrict__ dst) {
    int e = blockIdx.x * blockDim.x + threadIdx.x;
    if (e < N_EDGES) {
        int d = dst[e];
        int p = atomicAdd(&g_cursor[d], 1);
        g_col[p] = src[e];
    }
}

// ---------------- tf32 helpers ----------------
__device__ __forceinline__ uint32_t f2tf32(float v) {
    uint32_t u;
    asm("cvt.rna.tf32.f32 %0, %1;" : "=r"(u) : "f"(v));
    return u;
}

__device__ __forceinline__ void mma_tf32(float& c0, float& c1, float& c2, float& c3,
                                         uint32_t a0, uint32_t a1, uint32_t a2, uint32_t a3,
                                         uint32_t b0, uint32_t b1) {
    asm volatile(
        "mma.sync.aligned.m16n8k8.row.col.f32.tf32.tf32.f32 "
        "{%0,%1,%2,%3}, {%4,%5,%6,%7}, {%8,%9}, {%0,%1,%2,%3};"
        : "+f"(c0), "+f"(c1), "+f"(c2), "+f"(c3)
        : "r"(a0), "r"(a1), "r"(a2), "r"(a3), "r"(b0), "r"(b1));
}

// ---------------- GEMM (tf32 tensor cores): g_h = (A @ W) * dis[row] ----------------
// 128x128 block tile, BK=16, 8 warps (warp tile 32x64 via m16n8k8), 256 threads.
// As[row][k] stride 20, Wt[col][k] stride 20 -> conflict-free fragment LDS.
template <int K, bool FROM_X>
__global__ void __launch_bounds__(256, 2) k_gemm_tc(const float* __restrict__ Aext,
                                                    const float* __restrict__ W) {
    __shared__ uint32_t As[128 * 20];
    __shared__ uint32_t Wt[128 * 20];

    const float* A = FROM_X ? Aext : g_h2;
    const int tid = threadIdx.x;
    const int lane = tid & 31;
    const int wid = tid >> 5;
    const int warp_m = wid & 3;      // 0..3 -> 32 rows each
    const int warp_n = wid >> 2;     // 0..1 -> 64 cols each
    const int row0 = blockIdx.x * 128;
    const int lq = lane >> 2;        // lane/4: 0..7
    const int lr = lane & 3;         // lane%4: 0..3

    float acc[2][8][4];
    #pragma unroll
    for (int mt = 0; mt < 2; mt++)
        #pragma unroll
        for (int nt = 0; nt < 8; nt++)
            #pragma unroll
            for (int i = 0; i < 4; i++) acc[mt][nt][i] = 0.f;

    for (int kk = 0; kk < K; kk += 16) {
        // A tile: 128 rows x 16 k = 512 float4 loads, 2 per thread
        #pragma unroll
        for (int j = 0; j < 2; j++) {
            int f = tid + 256 * j;           // 0..511
            int r = f >> 2;                  // 0..127
            int k4 = (f & 3) * 4;            // 0,4,8,12
            int row = row0 + r;
            float4 v = make_float4(0.f, 0.f, 0.f, 0.f);
            if (row < N_NODES) v = *(const float4*)&A[row * K + kk + k4];
            As[r * 20 + k4 + 0] = f2tf32(v.x);
            As[r * 20 + k4 + 1] = f2tf32(v.y);
            As[r * 20 + k4 + 2] = f2tf32(v.z);
            As[r * 20 + k4 + 3] = f2tf32(v.w);
        }
        // W tile: 16 k x 128 n, stored transposed Wt[n][k]
        #pragma unroll
        for (int j = 0; j < 2; j++) {
            int f = tid + 256 * j;           // 0..511
            int kr = f >> 5;                 // 0..15
            int n4 = (f & 31) * 4;           // 0..124
            float4 v = *(const float4*)&W[(kk + kr) * HID + n4];
            Wt[(n4 + 0) * 20 + kr] = f2tf32(v.x);
            Wt[(n4 + 1) * 20 + kr] = f2tf32(v.y);
            Wt[(n4 + 2) * 20 + kr] = f2tf32(v.z);
            Wt[(n4 + 3) * 20 + kr] = f2tf32(v.w);
        }
        __syncthreads();

        #pragma unroll
        for (int ks = 0; ks < 16; ks += 8) {
            uint32_t afr[2][4];
            #pragma unroll
            for (int mt = 0; mt < 2; mt++) {
                int rbase = (warp_m * 32 + mt * 16 + lq) * 20;
                afr[mt][0] = As[rbase + ks + lr];
                afr[mt][1] = As[rbase + 8 * 20 + ks + lr];
                afr[mt][2] = As[rbase + ks + 4 + lr];
                afr[mt][3] = As[rbase + 8 * 20 + ks + 4 + lr];
            }
            #pragma unroll
            for (int nt = 0; nt < 8; nt++) {
                int cbase = (warp_n * 64 + nt * 8 + lq) * 20;
                uint32_t b0 = Wt[cbase + ks + lr];
                uint32_t b1 = Wt[cbase + ks + 4 + lr];
                #pragma unroll
                for (int mt = 0; mt < 2; mt++) {
                    mma_tf32(acc[mt][nt][0], acc[mt][nt][1], acc[mt][nt][2], acc[mt][nt][3],
                             afr[mt][0], afr[mt][1], afr[mt][2], afr[mt][3], b0, b1);
                }
            }
        }
        __syncthreads();
    }

    // epilogue: scale by dis[row], write hs
    #pragma unroll
    for (int mt = 0; mt < 2; mt++) {
        int r0 = row0 + warp_m * 32 + mt * 16 + lq;
        int r1 = r0 + 8;
        float d0 = (r0 < N_NODES) ? g_dis[r0] : 0.f;
        float d1 = (r1 < N_NODES) ? g_dis[r1] : 0.f;
        #pragma unroll
        for (int nt = 0; nt < 8; nt++) {
            int col = warp_n * 64 + nt * 8 + lr * 2;
            if (r0 < N_NODES) {
                float2 o = make_float2(acc[mt][nt][0] * d0, acc[mt][nt][1] * d0);
                *(float2*)&g_h[r0 * HID + col] = o;
            }
            if (r1 < N_NODES) {
                float2 o = make_float2(acc[mt][nt][2] * d1, acc[mt][nt][3] * d1);
                *(float2*)&g_h[r1 * HID + col] = o;
            }
        }
    }
}

// ---------------- edge aggregation (pull, CSR, warp per node) ----------------
__global__ void k_agg(const float* __restrict__ bias) {
    int node = (blockIdx.x * blockDim.x + threadIdx.x) >> 5;
    int lane = threadIdx.x & 31;
    if (node >= N_NODES) return;

    const float4* hs4 = (const float4*)g_h;
    int beg = g_row_ptr[node];
    int end = g_row_ptr[node + 1];

    float4 a0 = hs4[node * 32 + lane];
    float4 a1 = make_float4(0.f, 0.f, 0.f, 0.f);
    float4 a2 = make_float4(0.f, 0.f, 0.f, 0.f);
    float4 a3 = make_float4(0.f, 0.f, 0.f, 0.f);

    int e = beg;
    for (; e + 4 <= end; e += 4) {
        int s0 = g_col[e + 0];
        int s1 = g_col[e + 1];
        int s2 = g_col[e + 2];
        int s3 = g_col[e + 3];
        float4 v0 = hs4[s0 * 32 + lane];
        float4 v1 = hs4[s1 * 32 + lane];
        float4 v2 = hs4[s2 * 32 + lane];
        float4 v3 = hs4[s3 * 32 + lane];
        a0.x += v0.x; a0.y += v0.y; a0.z += v0.z; a0.w += v0.w;
        a1.x += v1.x; a1.y += v1.y; a1.z += v1.z; a1.w += v1.w;
        a2.x += v2.x; a2.y += v2.y; a2.z += v2.z; a2.w += v2.w;
        a3.x += v3.x; a3.y += v3.y; a3.z += v3.z; a3.w += v3.w;
    }
    for (; e < end; e++) {
        int s = g_col[e];
        float4 v = hs4[s * 32 + lane];
        a0.x += v.x; a0.y += v.y; a0.z += v.z; a0.w += v.w;
    }
    a0.x += a1.x + a2.x + a3.x;
    a0.y += a1.y + a2.y + a3.y;
    a0.z += a1.z + a2.z + a3.z;
    a0.w += a1.w + a2.w + a3.w;

    float d = g_dis[node];
    float4 bb = ((const float4*)bias)[lane];
    float4 r;
    r.x = fmaxf(fmaf(d, a0.x, bb.x), 0.f);
    r.y = fmaxf(fmaf(d, a0.y, bb.y), 0.f);
    r.z = fmaxf(fmaf(d, a0.z, bb.z), 0.f);
    r.w = fmaxf(fmaf(d, a0.w, bb.w), 0.f);
    ((float4*)g_h2)[node * 32 + lane] = r;
}

// ---------------- pooling: segment sums over sorted batch ----------------
__global__ void k_pool(const int* __restrict__ batch) {
    const int col = threadIdx.x;          // 0..127
    const int n0 = blockIdx.x * 128;
    const int nend = min(n0 + 128, N_NODES);
    if (n0 >= N_NODES) return;

    float acc = 0.f;
    int cnt = 0;
    int cur = batch[n0];
    for (int nd = n0; nd < nend; nd++) {
        int g = batch[nd];
        if (g != cur) {
            atomicAdd(&g_pool[cur * HID + col], acc);
            if (col == 0) atomicAdd(&g_cnt[cur], cnt);
            acc = 0.f; cnt = 0; cur = g;
        }
        acc += g_h2[nd * HID + col];
        cnt++;
    }
    atomicAdd(&g_pool[cur * HID + col], acc);
    if (col == 0) atomicAdd(&g_cnt[cur], cnt);
}

__global__ void k_pdiv() {
    int idx = blockIdx.x * blockDim.x + threadIdx.x;
    if (idx < N_GRAPHS * HID) {
        float c = (float)g_cnt[idx / HID];
        g_pooled[idx] = g_pool[idx] / fmaxf(c, 1.0f);
    }
}

// ---------------- output heads ----------------
__global__ void k_heads(const float* __restrict__ Wmf, const float* __restrict__ bmf,
                        const float* __restrict__ Wbp, const float* __restrict__ bbp,
                        const float* __restrict__ Wcc, const float* __restrict__ bcc,
                        float* __restrict__ out) {
    const int TOT = OUT_MF + OUT_BP + OUT_CC;  // 2752
    int idx = blockIdx.x * blockDim.x + threadIdx.x;
    if (idx >= N_GRAPHS * TOT) return;
    int g = idx / TOT;
    int c = idx % TOT;

    const float* W;
    const float* b;
    float* o;
    int od, cc;
    if (c < OUT_MF) {
        W = Wmf; b = bmf; od = OUT_MF; cc = c;
        o = out;
    } else if (c < OUT_MF + OUT_BP) {
        W = Wbp; b = bbp; od = OUT_BP; cc = c - OUT_MF;
        o = out + N_GRAPHS * OUT_MF;
    } else {
        W = Wcc; b = bcc; od = OUT_CC; cc = c - OUT_MF - OUT_BP;
        o = out + N_GRAPHS * (OUT_MF + OUT_BP);
    }

    const float* p = g_pooled + g * HID;
    float acc = b[cc];
    #pragma unroll 8
    for (int k = 0; k < HID; k++) acc = fmaf(p[k], W[k * od + cc], acc);
    o[g * od + cc] = acc;
}

// ---------------- launch ----------------
extern "C" void kernel_launch(void* const* d_in, const int* in_sizes, int n_in,
                              void* d_out, int out_size) {
    const float* x    = (const float*)d_in[0];
    const int*   ei   = (const int*)d_in[1];
    const int*   bat  = (const int*)d_in[2];
    const float* W1   = (const float*)d_in[3];
    const float* b1   = (const float*)d_in[4];
    const float* W2   = (const float*)d_in[5];
    const float* b2   = (const float*)d_in[6];
    const float* Wmf  = (const float*)d_in[7];
    const float* bmf  = (const float*)d_in[8];
    const float* Wbp  = (const float*)d_in[9];
    const float* bbp  = (const float*)d_in[10];
    const float* Wcc  = (const float*)d_in[11];
    const float* bcc  = (const float*)d_in[12];
    float* out = (float*)d_out;

    const int* src = ei;
    const int* dst = ei + N_EDGES;

    const int EBLK = (N_EDGES + 255) / 256;
    const int GEMM_BLOCKS = (N_NODES + 127) / 128;

    k_zero<<<512, 256>>>();
    k_count<<<EBLK, 256>>>(dst);
    k_scan<<<1, 1024>>>();
    k_fill<<<EBLK, 256>>>(src, dst);

    // layer 1
    k_gemm_tc<IN_DIM, true><<<GEMM_BLOCKS, 256>>>(x, W1);
    k_agg<<<(N_NODES * 32 + 255) / 256, 256>>>(b1);

    // layer 2
    k_gemm_tc<HID, false><<<GEMM_BLOCKS, 256>>>(nullptr, W2);
    k_agg<<<(N_NODES * 32 + 255) / 256, 256>>>(b2);

    // pool + heads
    k_pool<<<(N_NODES + 127) / 128, 128>>>(bat);
    k_pdiv<<<(N_GRAPHS * HID + 255) / 256, 256>>>();
    k_heads<<<(N_GRAPHS * (OUT_MF + OUT_BP + OUT_CC) + 255) / 256, 256>>>(
        Wmf, bmf, Wbp, bbp, Wcc, bcc, out);
}

// round 4
// speedup vs baseline: 1.4527x; 1.2512x over previous
#include <cuda_runtime.h>
#include <cuda_bf16.h>
#include <cstdint>

#define N_NODES 100000
#define N_EDGES 1600000
#define IN_DIM 256
#define HID 128
#define N_GRAPHS 64
#define OUT_MF 489
#define OUT_BP 1943
#define OUT_CC 320

#define NPART 25  // ceil(100000/4096)

// ---------------- scratch (device globals; no runtime alloc) ----------------
__device__ __align__(16) __nv_bfloat16 g_h[N_NODES * HID];  // hs (pre-scaled, bf16)
__device__ __align__(16) float g_h2[N_NODES * HID];         // activated layer out (fp32)
__device__ float g_dis[N_NODES];
__device__ int   g_deg[N_NODES];
__device__ int   g_row_ptr[N_NODES + 1];
__device__ int   g_cursor[N_NODES];
__device__ int   g_col[N_EDGES];
__device__ int   g_part[NPART];
__device__ int   g_pbase[NPART];
__device__ __align__(16) float g_pool[N_GRAPHS * HID];
__device__ __align__(16) float g_pooled[N_GRAPHS * HID];
__device__ int   g_cnt[N_GRAPHS];

// ---------------- zero init (graph-replay safe) ----------------
__global__ void k_zero() {
    int idx = blockIdx.x * blockDim.x + threadIdx.x;
    int stride = gridDim.x * blockDim.x;
    for (int i = idx; i < N_NODES; i += stride) g_deg[i] = 0;
    if (idx < N_GRAPHS * HID) g_pool[idx] = 0.f;
    if (idx < N_GRAPHS) g_cnt[idx] = 0;
}

// ---------------- in-degree count (4 edges/thread, int4 loads) ----------------
__global__ void k_count(const int* __restrict__ dst) {
    int t = blockIdx.x * blockDim.x + threadIdx.x;
    int e = t * 4;
    if (e + 4 <= N_EDGES) {
        int4 d = *(const int4*)&dst[e];
        atomicAdd(&g_deg[d.x], 1);
        atomicAdd(&g_deg[d.y], 1);
        atomicAdd(&g_deg[d.z], 1);
        atomicAdd(&g_deg[d.w], 1);
    } else {
        for (int i = e; i < N_EDGES; i++) atomicAdd(&g_deg[dst[i]], 1);
    }
}

// ---------------- parallel exclusive scan over degrees (3 phases) ----------------
__global__ void k_scan_a() {
    __shared__ int warp_sums[32];
    const int tid = threadIdx.x;
    const int lane = tid & 31;
    const int wid = tid >> 5;
    const int i0 = blockIdx.x * 4096 + tid * 4;

    int v0 = (i0 + 0 < N_NODES) ? g_deg[i0 + 0] : 0;
    int v1 = (i0 + 1 < N_NODES) ? g_deg[i0 + 1] : 0;
    int v2 = (i0 + 2 < N_NODES) ? g_deg[i0 + 2] : 0;
    int v3 = (i0 + 3 < N_NODES) ? g_deg[i0 + 3] : 0;
    int t = v0 + v1 + v2 + v3;

    int x = t;
    #pragma unroll
    for (int s = 1; s < 32; s <<= 1) {
        int y = __shfl_up_sync(0xFFFFFFFFu, x, s);
        if (lane >= s) x += y;
    }
    if (lane == 31) warp_sums[wid] = x;
    __syncthreads();
    if (wid == 0) {
        int w = warp_sums[lane];
        #pragma unroll
        for (int s = 1; s < 32; s <<= 1) {
            int y = __shfl_up_sync(0xFFFFFFFFu, w, s);
            if (lane >= s) w += y;
        }
        warp_sums[lane] = w;
    }
    __syncthreads();

    int warp_excl = (wid == 0) ? 0 : warp_sums[wid - 1];
    int off = warp_excl + (x - t);  // block-local exclusive offset

    int e0 = off;
    int e1 = e0 + v0;
    int e2 = e1 + v1;
    int e3 = e2 + v2;
    if (i0 + 0 < N_NODES) { g_row_ptr[i0 + 0] = e0; g_dis[i0 + 0] = rsqrtf((float)v0 + 1.0f); }
    if (i0 + 1 < N_NODES) { g_row_ptr[i0 + 1] = e1; g_dis[i0 + 1] = rsqrtf((float)v1 + 1.0f); }
    if (i0 + 2 < N_NODES) { g_row_ptr[i0 + 2] = e2; g_dis[i0 + 2] = rsqrtf((float)v2 + 1.0f); }
    if (i0 + 3 < N_NODES) { g_row_ptr[i0 + 3] = e3; g_dis[i0 + 3] = rsqrtf((float)v3 + 1.0f); }

    if (tid == 0) g_part[blockIdx.x] = warp_sums[31];
}

__global__ void k_scan_b() {
    int lane = threadIdx.x;
    int v = (lane < NPART) ? g_part[lane] : 0;
    int x = v;
    #pragma unroll
    for (int s = 1; s < 32; s <<= 1) {
        int y = __shfl_up_sync(0xFFFFFFFFu, x, s);
        if (lane >= s) x += y;
    }
    if (lane < NPART) g_pbase[lane] = x - v;
    if (lane == NPART - 1) g_row_ptr[N_NODES] = x;
}

__global__ void k_scan_c() {
    int baseval = g_pbase[blockIdx.x];
    int i0 = blockIdx.x * 4096 + threadIdx.x * 4;
    #pragma unroll
    for (int j = 0; j < 4; j++) {
        int i = i0 + j;
        if (i < N_NODES) {
            int r = g_row_ptr[i] + baseval;
            g_row_ptr[i] = r;
            g_cursor[i] = r;
        }
    }
}

// ---------------- CSR fill (4 edges/thread) ----------------
__global__ void k_fill(const int* __restrict__ src, const int* __restrict__ dst) {
    int t = blockIdx.x * blockDim.x + threadIdx.x;
    int e = t * 4;
    if (e + 4 <= N_EDGES) {
        int4 d = *(const int4*)&dst[e];
        int4 s = *(const int4*)&src[e];
        g_col[atomicAdd(&g_cursor[d.x], 1)] = s.x;
        g_col[atomicAdd(&g_cursor[d.y], 1)] = s.y;
        g_col[atomicAdd(&g_cursor[d.z], 1)] = s.z;
        g_col[atomicAdd(&g_cursor[d.w], 1)] = s.w;
    } else {
        for (int i = e; i < N_EDGES; i++)
            g_col[atomicAdd(&g_cursor[dst[i]], 1)] = src[i];
    }
}

// ---------------- tf32 helpers ----------------
__device__ __forceinline__ uint32_t f2tf32(float v) {
    uint32_t u;
    asm("cvt.rna.tf32.f32 %0, %1;" : "=r"(u) : "f"(v));
    return u;
}

__device__ __forceinline__ void mma_tf32(float& c0, float& c1, float& c2, float& c3,
                                         uint32_t a0, uint32_t a1, uint32_t a2, uint32_t a3,
                                         uint32_t b0, uint32_t b1) {
    asm volatile(
        "mma.sync.aligned.m16n8k8.row.col.f32.tf32.tf32.f32 "
        "{%0,%1,%2,%3}, {%4,%5,%6,%7}, {%8,%9}, {%0,%1,%2,%3};"
        : "+f"(c0), "+f"(c1), "+f"(c2), "+f"(c3)
        : "r"(a0), "r"(a1), "r"(a2), "r"(a3), "r"(b0), "r"(b1));
}

// ---------------- GEMM (tf32): g_h = bf16((A @ W) * dis[row]) ----------------
// 128x128 block tile, BK=16, 8 warps (warp tile 32x64 via m16n8k8), 256 threads.
template <int K, bool FROM_X>
__global__ void __launch_bounds__(256, 2) k_gemm_tc(const float* __restrict__ Aext,
                                                    const float* __restrict__ W) {
    __shared__ uint32_t As[128 * 20];
    __shared__ uint32_t Wt[128 * 20];

    const float* A = FROM_X ? Aext : g_h2;
    const int tid = threadIdx.x;
    const int lane = tid & 31;
    const int wid = tid >> 5;
    const int warp_m = wid & 3;
    const int warp_n = wid >> 2;
    const int row0 = blockIdx.x * 128;
    const int lq = lane >> 2;
    const int lr = lane & 3;

    float acc[2][8][4];
    #pragma unroll
    for (int mt = 0; mt < 2; mt++)
        #pragma unroll
        for (int nt = 0; nt < 8; nt++)
            #pragma unroll
            for (int i = 0; i < 4; i++) acc[mt][nt][i] = 0.f;

    for (int kk = 0; kk < K; kk += 16) {
        #pragma unroll
        for (int j = 0; j < 2; j++) {
            int f = tid + 256 * j;
            int r = f >> 2;
            int k4 = (f & 3) * 4;
            int row = row0 + r;
            float4 v = make_float4(0.f, 0.f, 0.f, 0.f);
            if (row < N_NODES) v = *(const float4*)&A[row * K + kk + k4];
            As[r * 20 + k4 + 0] = f2tf32(v.x);
            As[r * 20 + k4 + 1] = f2tf32(v.y);
            As[r * 20 + k4 + 2] = f2tf32(v.z);
            As[r * 20 + k4 + 3] = f2tf32(v.w);
        }
        #pragma unroll
        for (int j = 0; j < 2; j++) {
            int f = tid + 256 * j;
            int kr = f >> 5;
            int n4 = (f & 31) * 4;
            float4 v = *(const float4*)&W[(kk + kr) * HID + n4];
            Wt[(n4 + 0) * 20 + kr] = f2tf32(v.x);
            Wt[(n4 + 1) * 20 + kr] = f2tf32(v.y);
            Wt[(n4 + 2) * 20 + kr] = f2tf32(v.z);
            Wt[(n4 + 3) * 20 + kr] = f2tf32(v.w);
        }
        __syncthreads();

        #pragma unroll
        for (int ks = 0; ks < 16; ks += 8) {
            uint32_t afr[2][4];
            #pragma unroll
            for (int mt = 0; mt < 2; mt++) {
                int rbase = (warp_m * 32 + mt * 16 + lq) * 20;
                afr[mt][0] = As[rbase + ks + lr];
                afr[mt][1] = As[rbase + 8 * 20 + ks + lr];
                afr[mt][2] = As[rbase + ks + 4 + lr];
                afr[mt][3] = As[rbase + 8 * 20 + ks + 4 + lr];
            }
            #pragma unroll
            for (int nt = 0; nt < 8; nt++) {
                int cbase = (warp_n * 64 + nt * 8 + lq) * 20;
                uint32_t b0 = Wt[cbase + ks + lr];
                uint32_t b1 = Wt[cbase + ks + 4 + lr];
                #pragma unroll
                for (int mt = 0; mt < 2; mt++) {
                    mma_tf32(acc[mt][nt][0], acc[mt][nt][1], acc[mt][nt][2], acc[mt][nt][3],
                             afr[mt][0], afr[mt][1], afr[mt][2], afr[mt][3], b0, b1);
                }
            }
        }
        __syncthreads();
    }

    // epilogue: scale by dis[row], convert to bf16, write hs
    #pragma unroll
    for (int mt = 0; mt < 2; mt++) {
        int r0 = row0 + warp_m * 32 + mt * 16 + lq;
        int r1 = r0 + 8;
        float d0 = (r0 < N_NODES) ? g_dis[r0] : 0.f;
        float d1 = (r1 < N_NODES) ? g_dis[r1] : 0.f;
        #pragma unroll
        for (int nt = 0; nt < 8; nt++) {
            int col = warp_n * 64 + nt * 8 + lr * 2;
            if (r0 < N_NODES) {
                __nv_bfloat162 o = __float22bfloat162_rn(
                    make_float2(acc[mt][nt][0] * d0, acc[mt][nt][1] * d0));
                *(__nv_bfloat162*)&g_h[r0 * HID + col] = o;
            }
            if (r1 < N_NODES) {
                __nv_bfloat162 o = __float22bfloat162_rn(
                    make_float2(acc[mt][nt][2] * d1, acc[mt][nt][3] * d1));
                *(__nv_bfloat162*)&g_h[r1 * HID + col] = o;
            }
        }
    }
}

// ---------------- edge aggregation (pull, CSR, warp per node, bf16 gather) ----------------
__device__ __forceinline__ void acc_bf16x4(float4& a, uint2 v) {
    float2 f0 = __bfloat1622float2(*(const __nv_bfloat162*)&v.x);
    float2 f1 = __bfloat1622float2(*(const __nv_bfloat162*)&v.y);
    a.x += f0.x; a.y += f0.y; a.z += f1.x; a.w += f1.y;
}

__global__ void k_agg(const float* __restrict__ bias) {
    int node = (blockIdx.x * blockDim.x + threadIdx.x) >> 5;
    int lane = threadIdx.x & 31;
    if (node >= N_NODES) return;

    const uint2* hs = (const uint2*)g_h;  // 4 bf16 per uint2; 32 per row
    int beg = g_row_ptr[node];
    int end = g_row_ptr[node + 1];

    float4 a0 = make_float4(0.f, 0.f, 0.f, 0.f);
    float4 a1 = make_float4(0.f, 0.f, 0.f, 0.f);
    float4 a2 = make_float4(0.f, 0.f, 0.f, 0.f);
    float4 a3 = make_float4(0.f, 0.f, 0.f, 0.f);
    acc_bf16x4(a0, hs[node * 32 + lane]);  // self

    int e = beg;
    for (; e + 4 <= end; e += 4) {
        int s0 = g_col[e + 0];
        int s1 = g_col[e + 1];
        int s2 = g_col[e + 2];
        int s3 = g_col[e + 3];
        uint2 v0 = hs[s0 * 32 + lane];
        uint2 v1 = hs[s1 * 32 + lane];
        uint2 v2 = hs[s2 * 32 + lane];
        uint2 v3 = hs[s3 * 32 + lane];
        acc_bf16x4(a0, v0);
        acc_bf16x4(a1, v1);
        acc_bf16x4(a2, v2);
        acc_bf16x4(a3, v3);
    }
    for (; e < end; e++) {
        acc_bf16x4(a0, hs[g_col[e] * 32 + lane]);
    }
    a0.x += a1.x + a2.x + a3.x;
    a0.y += a1.y + a2.y + a3.y;
    a0.z += a1.z + a2.z + a3.z;
    a0.w += a1.w + a2.w + a3.w;

    float d = g_dis[node];
    float4 bb = ((const float4*)bias)[lane];
    float4 r;
    r.x = fmaxf(fmaf(d, a0.x, bb.x), 0.f);
    r.y = fmaxf(fmaf(d, a0.y, bb.y), 0.f);
    r.z = fmaxf(fmaf(d, a0.z, bb.z), 0.f);
    r.w = fmaxf(fmaf(d, a0.w, bb.w), 0.f);
    ((float4*)g_h2)[node * 32 + lane] = r;
}

// ---------------- pooling: segment sums over sorted batch ----------------
__global__ void k_pool(const int* __restrict__ batch) {
    const int col = threadIdx.x;
    const int n0 = blockIdx.x * 128;
    const int nend = min(n0 + 128, N_NODES);
    if (n0 >= N_NODES) return;

    float acc = 0.f;
    int cnt = 0;
    int cur = batch[n0];
    for (int nd = n0; nd < nend; nd++) {
        int g = batch[nd];
        if (g != cur) {
            atomicAdd(&g_pool[cur * HID + col], acc);
            if (col == 0) atomicAdd(&g_cnt[cur], cnt);
            acc = 0.f; cnt = 0; cur = g;
        }
        acc += g_h2[nd * HID + col];
        cnt++;
    }
    atomicAdd(&g_pool[cur * HID + col], acc);
    if (col == 0) atomicAdd(&g_cnt[cur], cnt);
}

__global__ void k_pdiv() {
    int idx = blockIdx.x * blockDim.x + threadIdx.x;
    if (idx < N_GRAPHS * HID) {
        float c = (float)g_cnt[idx / HID];
        g_pooled[idx] = g_pool[idx] / fmaxf(c, 1.0f);
    }
}

// ---------------- output heads ----------------
__global__ void k_heads(const float* __restrict__ Wmf, const float* __restrict__ bmf,
                        const float* __restrict__ Wbp, const float* __restrict__ bbp,
                        const float* __restrict__ Wcc, const float* __restrict__ bcc,
                        float* __restrict__ out) {
    const int TOT = OUT_MF + OUT_BP + OUT_CC;
    int idx = blockIdx.x * blockDim.x + threadIdx.x;
    if (idx >= N_GRAPHS * TOT) return;
    int g = idx / TOT;
    int c = idx % TOT;

    const float* W;
    const float* b;
    float* o;
    int od, cc;
    if (c < OUT_MF) {
        W = Wmf; b = bmf; od = OUT_MF; cc = c;
        o = out;
    } else if (c < OUT_MF + OUT_BP) {
        W = Wbp; b = bbp; od = OUT_BP; cc = c - OUT_MF;
        o = out + N_GRAPHS * OUT_MF;
    } else {
        W = Wcc; b = bcc; od = OUT_CC; cc = c - OUT_MF - OUT_BP;
        o = out + N_GRAPHS * (OUT_MF + OUT_BP);
    }

    const float* p = g_pooled + g * HID;
    float acc = b[cc];
    #pragma unroll 8
    for (int k = 0; k < HID; k++) acc = fmaf(p[k], W[k * od + cc], acc);
    o[g * od + cc] = acc;
}

// ---------------- launch (single stream, capture-safe) ----------------
extern "C" void kernel_launch(void* const* d_in, const int* in_sizes, int n_in,
                              void* d_out, int out_size) {
    const float* x    = (const float*)d_in[0];
    const int*   ei   = (const int*)d_in[1];
    const int*   bat  = (const int*)d_in[2];
    const float* W1   = (const float*)d_in[3];
    const float* b1   = (const float*)d_in[4];
    const float* W2   = (const float*)d_in[5];
    const float* b2   = (const float*)d_in[6];
    const float* Wmf  = (const float*)d_in[7];
    const float* bmf  = (const float*)d_in[8];
    const float* Wbp  = (const float*)d_in[9];
    const float* bbp  = (const float*)d_in[10];
    const float* Wcc  = (const float*)d_in[11];
    const float* bcc  = (const float*)d_in[12];
    float* out = (float*)d_out;

    const int* src = ei;
    const int* dst = ei + N_EDGES;

    const int EBLK4 = (N_EDGES / 4 + 255) / 256;
    const int GEMM_BLOCKS = (N_NODES + 127) / 128;

    // CSR build
    k_zero<<<512, 256>>>();
    k_count<<<EBLK4, 256>>>(dst);
    k_scan_a<<<NPART, 1024>>>();
    k_scan_b<<<1, 32>>>();
    k_scan_c<<<NPART, 1024>>>();
    k_fill<<<EBLK4, 256>>>(src, dst);

    // layer 1
    k_gemm_tc<IN_DIM, true><<<GEMM_BLOCKS, 256>>>(x, W1);
    k_agg<<<(N_NODES * 32 + 255) / 256, 256>>>(b1);

    // layer 2
    k_gemm_tc<HID, false><<<GEMM_BLOCKS, 256>>>(nullptr, W2);
    k_agg<<<(N_NODES * 32 + 255) / 256, 256>>>(b2);

    // pool + heads
    k_pool<<<(N_NODES + 127) / 128, 128>>>(bat);
    k_pdiv<<<(N_GRAPHS * HID + 255) / 256, 256>>>();
    k_heads<<<(N_GRAPHS * (OUT_MF + OUT_BP + OUT_CC) + 255) / 256, 256>>>(
        Wmf, bmf, Wbp, bbp, Wcc, bcc, out);
}

// round 5
// speedup vs baseline: 1.5402x; 1.0602x over previous
#include <cuda_runtime.h>
#include <cuda_bf16.h>
#include <cstdint>

#define N_NODES 100000
#define N_EDGES 1600000
#define IN_DIM 256
#define HID 128
#define N_GRAPHS 64
#define OUT_MF 489
#define OUT_BP 1943
#define OUT_CC 320

#define NPART 25  // ceil(100000/4096)

// ---------------- scratch (device globals; no runtime alloc) ----------------
__device__ __align__(16) __nv_bfloat16 g_h[N_NODES * HID];  // hs (pre-scaled, bf16)
__device__ __align__(16) float g_h2[N_NODES * HID];         // activated layer out (fp32)
__device__ float g_dis[N_NODES];
__device__ int   g_deg[N_NODES];
__device__ int   g_row_ptr[N_NODES + 1];
__device__ int   g_cursor[N_NODES];
__device__ int   g_col[N_EDGES];
__device__ int   g_part[NPART];
__device__ int   g_pbase[NPART];
__device__ __align__(16) float g_pool[N_GRAPHS * HID];
__device__ __align__(16) float g_pooled[N_GRAPHS * HID];
__device__ int   g_cnt[N_GRAPHS];

// ---------------- zero init (graph-replay safe) ----------------
__global__ void k_zero() {
    int idx = blockIdx.x * blockDim.x + threadIdx.x;
    int stride = gridDim.x * blockDim.x;
    for (int i = idx; i < N_NODES; i += stride) g_deg[i] = 0;
    if (idx < N_GRAPHS * HID) g_pool[idx] = 0.f;
    if (idx < N_GRAPHS) g_cnt[idx] = 0;
}

// ---------------- in-degree count (4 edges/thread, int4 loads) ----------------
__global__ void k_count(const int* __restrict__ dst) {
    int t = blockIdx.x * blockDim.x + threadIdx.x;
    int e = t * 4;
    if (e + 4 <= N_EDGES) {
        int4 d = *(const int4*)&dst[e];
        atomicAdd(&g_deg[d.x], 1);
        atomicAdd(&g_deg[d.y], 1);
        atomicAdd(&g_deg[d.z], 1);
        atomicAdd(&g_deg[d.w], 1);
    } else {
        for (int i = e; i < N_EDGES; i++) atomicAdd(&g_deg[dst[i]], 1);
    }
}

// ---------------- parallel exclusive scan over degrees (3 phases) ----------------
__global__ void k_scan_a() {
    __shared__ int warp_sums[32];
    const int tid = threadIdx.x;
    const int lane = tid & 31;
    const int wid = tid >> 5;
    const int i0 = blockIdx.x * 4096 + tid * 4;

    int v0 = (i0 + 0 < N_NODES) ? g_deg[i0 + 0] : 0;
    int v1 = (i0 + 1 < N_NODES) ? g_deg[i0 + 1] : 0;
    int v2 = (i0 + 2 < N_NODES) ? g_deg[i0 + 2] : 0;
    int v3 = (i0 + 3 < N_NODES) ? g_deg[i0 + 3] : 0;
    int t = v0 + v1 + v2 + v3;

    int x = t;
    #pragma unroll
    for (int s = 1; s < 32; s <<= 1) {
        int y = __shfl_up_sync(0xFFFFFFFFu, x, s);
        if (lane >= s) x += y;
    }
    if (lane == 31) warp_sums[wid] = x;
    __syncthreads();
    if (wid == 0) {
        int w = warp_sums[lane];
        #pragma unroll
        for (int s = 1; s < 32; s <<= 1) {
            int y = __shfl_up_sync(0xFFFFFFFFu, w, s);
            if (lane >= s) w += y;
        }
        warp_sums[lane] = w;
    }
    __syncthreads();

    int warp_excl = (wid == 0) ? 0 : warp_sums[wid - 1];
    int off = warp_excl + (x - t);

    int e0 = off;
    int e1 = e0 + v0;
    int e2 = e1 + v1;
    int e3 = e2 + v2;
    if (i0 + 0 < N_NODES) { g_row_ptr[i0 + 0] = e0; g_dis[i0 + 0] = rsqrtf((float)v0 + 1.0f); }
    if (i0 + 1 < N_NODES) { g_row_ptr[i0 + 1] = e1; g_dis[i0 + 1] = rsqrtf((float)v1 + 1.0f); }
    if (i0 + 2 < N_NODES) { g_row_ptr[i0 + 2] = e2; g_dis[i0 + 2] = rsqrtf((float)v2 + 1.0f); }
    if (i0 + 3 < N_NODES) { g_row_ptr[i0 + 3] = e3; g_dis[i0 + 3] = rsqrtf((float)v3 + 1.0f); }

    if (tid == 0) g_part[blockIdx.x] = warp_sums[31];
}

__global__ void k_scan_b() {
    int lane = threadIdx.x;
    int v = (lane < NPART) ? g_part[lane] : 0;
    int x = v;
    #pragma unroll
    for (int s = 1; s < 32; s <<= 1) {
        int y = __shfl_up_sync(0xFFFFFFFFu, x, s);
        if (lane >= s) x += y;
    }
    if (lane < NPART) g_pbase[lane] = x - v;
    if (lane == NPART - 1) g_row_ptr[N_NODES] = x;
}

__global__ void k_scan_c() {
    int baseval = g_pbase[blockIdx.x];
    int i0 = blockIdx.x * 4096 + threadIdx.x * 4;
    #pragma unroll
    for (int j = 0; j < 4; j++) {
        int i = i0 + j;
        if (i < N_NODES) {
            int r = g_row_ptr[i] + baseval;
            g_row_ptr[i] = r;
            g_cursor[i] = r;
        }
    }
}

// ---------------- CSR fill (4 edges/thread) ----------------
__global__ void k_fill(const int* __restrict__ src, const int* __restrict__ dst) {
    int t = blockIdx.x * blockDim.x + threadIdx.x;
    int e = t * 4;
    if (e + 4 <= N_EDGES) {
        int4 d = *(const int4*)&dst[e];
        int4 s = *(const int4*)&src[e];
        g_col[atomicAdd(&g_cursor[d.x], 1)] = s.x;
        g_col[atomicAdd(&g_cursor[d.y], 1)] = s.y;
        g_col[atomicAdd(&g_cursor[d.z], 1)] = s.z;
        g_col[atomicAdd(&g_cursor[d.w], 1)] = s.w;
    } else {
        for (int i = e; i < N_EDGES; i++)
            g_col[atomicAdd(&g_cursor[dst[i]], 1)] = src[i];
    }
}

// ---------------- tf32 helpers ----------------
__device__ __forceinline__ uint32_t f2tf32(float v) {
    uint32_t u;
    asm("cvt.rna.tf32.f32 %0, %1;" : "=r"(u) : "f"(v));
    return u;
}

__device__ __forceinline__ void mma_tf32(float& c0, float& c1, float& c2, float& c3,
                                         uint32_t a0, uint32_t a1, uint32_t a2, uint32_t a3,
                                         uint32_t b0, uint32_t b1) {
    asm volatile(
        "mma.sync.aligned.m16n8k8.row.col.f32.tf32.tf32.f32 "
        "{%0,%1,%2,%3}, {%4,%5,%6,%7}, {%8,%9}, {%0,%1,%2,%3};"
        : "+f"(c0), "+f"(c1), "+f"(c2), "+f"(c3)
        : "r"(a0), "r"(a1), "r"(a2), "r"(a3), "r"(b0), "r"(b1));
}

__device__ __forceinline__ void cp_async16(uint32_t saddr, const void* gptr, int sz) {
    asm volatile("cp.async.ca.shared.global [%0], [%1], 16, %2;\n"
                 :: "r"(saddr), "l"(gptr), "r"(sz));
}
__device__ __forceinline__ void cp_commit() {
    asm volatile("cp.async.commit_group;\n" ::: "memory");
}
__device__ __forceinline__ void cp_wait0() {
    asm volatile("cp.async.wait_group 0;\n" ::: "memory");
}

// ---------------- GEMM (tf32, cp.async double-buffered) ----------------
// g_h = bf16((A @ W) * dis[row]); 128x128 tile, BK=16, 8 warps, 256 threads.
// A operand: raw fp32 bits fed to tf32 MMA (HW truncation). W: cvt.rna at store.
template <int K, bool FROM_X>
__global__ void __launch_bounds__(256, 2) k_gemm_tc(const float* __restrict__ Aext,
                                                    const float* __restrict__ W) {
    __shared__ uint32_t As[2][128 * 20];
    __shared__ uint32_t Wt[2][128 * 20];

    const float* A = FROM_X ? Aext : g_h2;
    const int tid = threadIdx.x;
    const int lane = tid & 31;
    const int wid = tid >> 5;
    const int warp_m = wid & 3;
    const int warp_n = wid >> 2;
    const int row0 = blockIdx.x * 128;
    const int lq = lane >> 2;
    const int lr = lane & 3;

    // per-thread cp.async geometry: f = tid + 256*j, j in {0,1}
    // row = f>>2 (4x16B chunks per 16-float row), chunk = f&3
    const int ar0 = tid >> 2;          // j=0 row (0..63)
    const int ac0 = (tid & 3) * 4;     // float offset in row
    const int ar1 = ar0 + 64;          // j=1 row (64..127)

    float4 wreg[2];

    auto load_A = [&](int stage, int kk) {
        {
            int row = row0 + ar0;
            uint32_t sa = (uint32_t)__cvta_generic_to_shared(&As[stage][ar0 * 20 + ac0]);
            cp_async16(sa, &A[(size_t)row * K + kk + ac0], (row < N_NODES) ? 16 : 0);
        }
        {
            int row = row0 + ar1;
            uint32_t sa = (uint32_t)__cvta_generic_to_shared(&As[stage][ar1 * 20 + ac0]);
            cp_async16(sa, &A[(size_t)row * K + kk + ac0], (row < N_NODES) ? 16 : 0);
        }
    };
    auto load_W_regs = [&](int kk) {
        #pragma unroll
        for (int j = 0; j < 2; j++) {
            int f = tid + 256 * j;
            int kr = f >> 5;
            int n4 = (f & 31) * 4;
            wreg[j] = *(const float4*)&W[(kk + kr) * HID + n4];
        }
    };
    auto store_W = [&](int stage) {
        #pragma unroll
        for (int j = 0; j < 2; j++) {
            int f = tid + 256 * j;
            int kr = f >> 5;
            int n4 = (f & 31) * 4;
            Wt[stage][(n4 + 0) * 20 + kr] = f2tf32(wreg[j].x);
            Wt[stage][(n4 + 1) * 20 + kr] = f2tf32(wreg[j].y);
            Wt[stage][(n4 + 2) * 20 + kr] = f2tf32(wreg[j].z);
            Wt[stage][(n4 + 3) * 20 + kr] = f2tf32(wreg[j].w);
        }
    };

    float acc[2][8][4];
    #pragma unroll
    for (int mt = 0; mt < 2; mt++)
        #pragma unroll
        for (int nt = 0; nt < 8; nt++)
            #pragma unroll
            for (int i = 0; i < 4; i++) acc[mt][nt][i] = 0.f;

    // prologue: stage 0
    load_A(0, 0);
    cp_commit();
    load_W_regs(0);
    store_W(0);
    cp_wait0();
    __syncthreads();

    const int NT = K / 16;
    for (int t = 0; t < NT; t++) {
        int cur = t & 1;
        int nxt = cur ^ 1;
        if (t + 1 < NT) {
            load_A(nxt, (t + 1) * 16);
            cp_commit();
            load_W_regs((t + 1) * 16);
        }

        // compute on stage cur
        #pragma unroll
        for (int ks = 0; ks < 16; ks += 8) {
            uint32_t afr[2][4];
            #pragma unroll
            for (int mt = 0; mt < 2; mt++) {
                int rbase = (warp_m * 32 + mt * 16 + lq) * 20;
                afr[mt][0] = As[cur][rbase + ks + lr];
                afr[mt][1] = As[cur][rbase + 8 * 20 + ks + lr];
                afr[mt][2] = As[cur][rbase + ks + 4 + lr];
                afr[mt][3] = As[cur][rbase + 8 * 20 + ks + 4 + lr];
            }
            #pragma unroll
            for (int nt = 0; nt < 8; nt++) {
                int cbase = (warp_n * 64 + nt * 8 + lq) * 20;
                uint32_t b0 = Wt[cur][cbase + ks + lr];
                uint32_t b1 = Wt[cur][cbase + ks + 4 + lr];
                #pragma unroll
                for (int mt = 0; mt < 2; mt++) {
                    mma_tf32(acc[mt][nt][0], acc[mt][nt][1], acc[mt][nt][2], acc[mt][nt][3],
                             afr[mt][0], afr[mt][1], afr[mt][2], afr[mt][3], b0, b1);
                }
            }
        }

        if (t + 1 < NT) {
            store_W(nxt);
            cp_wait0();
            __syncthreads();
        }
    }

    // epilogue: scale by dis[row], convert to bf16, write hs
    #pragma unroll
    for (int mt = 0; mt < 2; mt++) {
        int r0 = row0 + warp_m * 32 + mt * 16 + lq;
        int r1 = r0 + 8;
        float d0 = (r0 < N_NODES) ? g_dis[r0] : 0.f;
        float d1 = (r1 < N_NODES) ? g_dis[r1] : 0.f;
        #pragma unroll
        for (int nt = 0; nt < 8; nt++) {
            int col = warp_n * 64 + nt * 8 + lr * 2;
            if (r0 < N_NODES) {
                __nv_bfloat162 o = __float22bfloat162_rn(
                    make_float2(acc[mt][nt][0] * d0, acc[mt][nt][1] * d0));
                *(__nv_bfloat162*)&g_h[r0 * HID + col] = o;
            }
            if (r1 < N_NODES) {
                __nv_bfloat162 o = __float22bfloat162_rn(
                    make_float2(acc[mt][nt][2] * d1, acc[mt][nt][3] * d1));
                *(__nv_bfloat162*)&g_h[r1 * HID + col] = o;
            }
        }
    }
}

// ---------------- edge aggregation (pull, CSR, warp per node, bf16 gather) ----------------
__device__ __forceinline__ void acc_bf16x4(float4& a, uint2 v) {
    float2 f0 = __bfloat1622float2(*(const __nv_bfloat162*)&v.x);
    float2 f1 = __bfloat1622float2(*(const __nv_bfloat162*)&v.y);
    a.x += f0.x; a.y += f0.y; a.z += f1.x; a.w += f1.y;
}

__global__ void k_agg(const float* __restrict__ bias) {
    int node = (blockIdx.x * blockDim.x + threadIdx.x) >> 5;
    int lane = threadIdx.x & 31;
    if (node >= N_NODES) return;

    const uint2* hs = (const uint2*)g_h;
    int beg = g_row_ptr[node];
    int end = g_row_ptr[node + 1];

    float4 a0 = make_float4(0.f, 0.f, 0.f, 0.f);
    float4 a1 = make_float4(0.f, 0.f, 0.f, 0.f);
    float4 a2 = make_float4(0.f, 0.f, 0.f, 0.f);
    float4 a3 = make_float4(0.f, 0.f, 0.f, 0.f);
    acc_bf16x4(a0, hs[node * 32 + lane]);  // self

    int e = beg;
    for (; e + 4 <= end; e += 4) {
        int s0 = g_col[e + 0];
        int s1 = g_col[e + 1];
        int s2 = g_col[e + 2];
        int s3 = g_col[e + 3];
        uint2 v0 = hs[s0 * 32 + lane];
        uint2 v1 = hs[s1 * 32 + lane];
        uint2 v2 = hs[s2 * 32 + lane];
        uint2 v3 = hs[s3 * 32 + lane];
        acc_bf16x4(a0, v0);
        acc_bf16x4(a1, v1);
        acc_bf16x4(a2, v2);
        acc_bf16x4(a3, v3);
    }
    for (; e < end; e++) {
        acc_bf16x4(a0, hs[g_col[e] * 32 + lane]);
    }
    a0.x += a1.x + a2.x + a3.x;
    a0.y += a1.y + a2.y + a3.y;
    a0.z += a1.z + a2.z + a3.z;
    a0.w += a1.w + a2.w + a3.w;

    float d = g_dis[node];
    float4 bb = ((const float4*)bias)[lane];
    float4 r;
    r.x = fmaxf(fmaf(d, a0.x, bb.x), 0.f);
    r.y = fmaxf(fmaf(d, a0.y, bb.y), 0.f);
    r.z = fmaxf(fmaf(d, a0.z, bb.z), 0.f);
    r.w = fmaxf(fmaf(d, a0.w, bb.w), 0.f);
    ((float4*)g_h2)[node * 32 + lane] = r;
}

// ---------------- pooling: segment sums over sorted batch ----------------
__global__ void k_pool(const int* __restrict__ batch) {
    const int col = threadIdx.x;
    const int n0 = blockIdx.x * 128;
    const int nend = min(n0 + 128, N_NODES);
    if (n0 >= N_NODES) return;

    float acc = 0.f;
    int cnt = 0;
    int cur = batch[n0];
    for (int nd = n0; nd < nend; nd++) {
        int g = batch[nd];
        if (g != cur) {
            atomicAdd(&g_pool[cur * HID + col], acc);
            if (col == 0) atomicAdd(&g_cnt[cur], cnt);
            acc = 0.f; cnt = 0; cur = g;
        }
        acc += g_h2[nd * HID + col];
        cnt++;
    }
    atomicAdd(&g_pool[cur * HID + col], acc);
    if (col == 0) atomicAdd(&g_cnt[cur], cnt);
}

__global__ void k_pdiv() {
    int idx = blockIdx.x * blockDim.x + threadIdx.x;
    if (idx < N_GRAPHS * HID) {
        float c = (float)g_cnt[idx / HID];
        g_pooled[idx] = g_pool[idx] / fmaxf(c, 1.0f);
    }
}

// ---------------- output heads ----------------
__global__ void k_heads(const float* __restrict__ Wmf, const float* __restrict__ bmf,
                        const float* __restrict__ Wbp, const float* __restrict__ bbp,
                        const float* __restrict__ Wcc, const float* __restrict__ bcc,
                        float* __restrict__ out) {
    const int TOT = OUT_MF + OUT_BP + OUT_CC;
    int idx = blockIdx.x * blockDim.x + threadIdx.x;
    if (idx >= N_GRAPHS * TOT) return;
    int g = idx / TOT;
    int c = idx % TOT;

    const float* W;
    const float* b;
    float* o;
    int od, cc;
    if (c < OUT_MF) {
        W = Wmf; b = bmf; od = OUT_MF; cc = c;
        o = out;
    } else if (c < OUT_MF + OUT_BP) {
        W = Wbp; b = bbp; od = OUT_BP; cc = c - OUT_MF;
        o = out + N_GRAPHS * OUT_MF;
    } else {
        W = Wcc; b = bcc; od = OUT_CC; cc = c - OUT_MF - OUT_BP;
        o = out + N_GRAPHS * (OUT_MF + OUT_BP);
    }

    const float* p = g_pooled + g * HID;
    float acc = b[cc];
    #pragma unroll 8
    for (int k = 0; k < HID; k++) acc = fmaf(p[k], W[k * od + cc], acc);
    o[g * od + cc] = acc;
}

// ---------------- launch (single stream, capture-safe) ----------------
extern "C" void kernel_launch(void* const* d_in, const int* in_sizes, int n_in,
                              void* d_out, int out_size) {
    const float* x    = (const float*)d_in[0];
    const int*   ei   = (const int*)d_in[1];
    const int*   bat  = (const int*)d_in[2];
    const float* W1   = (const float*)d_in[3];
    const float* b1   = (const float*)d_in[4];
    const float* W2   = (const float*)d_in[5];
    const float* b2   = (const float*)d_in[6];
    const float* Wmf  = (const float*)d_in[7];
    const float* bmf  = (const float*)d_in[8];
    const float* Wbp  = (const float*)d_in[9];
    const float* bbp  = (const float*)d_in[10];
    const float* Wcc  = (const float*)d_in[11];
    const float* bcc  = (const float*)d_in[12];
    float* out = (float*)d_out;

    const int* src = ei;
    const int* dst = ei + N_EDGES;

    const int EBLK4 = (N_EDGES / 4 + 255) / 256;
    const int GEMM_BLOCKS = (N_NODES + 127) / 128;

    // CSR build
    k_zero<<<512, 256>>>();
    k_count<<<EBLK4, 256>>>(dst);
    k_scan_a<<<NPART, 1024>>>();
    k_scan_b<<<1, 32>>>();
    k_scan_c<<<NPART, 1024>>>();
    k_fill<<<EBLK4, 256>>>(src, dst);

    // layer 1
    k_gemm_tc<IN_DIM, true><<<GEMM_BLOCKS, 256>>>(x, W1);
    k_agg<<<(N_NODES * 32 + 255) / 256, 256>>>(b1);

    // layer 2
    k_gemm_tc<HID, false><<<GEMM_BLOCKS, 256>>>(nullptr, W2);
    k_agg<<<(N_NODES * 32 + 255) / 256, 256>>>(b2);

    // pool + heads
    k_pool<<<(N_NODES + 127) / 128, 128>>>(bat);
    k_pdiv<<<(N_GRAPHS * HID + 255) / 256, 256>>>();
    k_heads<<<(N_GRAPHS * (OUT_MF + OUT_BP + OUT_CC) + 255) / 256, 256>>>(
        Wmf, bmf, Wbp, bbp, Wcc, bcc, out);
}